// round 16
// baseline (speedup 1.0000x reference)
#include <cuda_runtime.h>
#include <cuda_bf16.h>
#include <cstdint>
#include <math.h>

#define B_ 2
#define T_ 4096
#define H_ 12
#define D_ 64
#define C_ 768
#define BT_ (B_*T_)
#define BH_ (B_*H_)
#define K2 2304   // 3 * C_ : [hi | lo | hi] x [hi | hi | lo]
#define D2 192    // 3 * D_ for attention QK split
#define N3 2304   // merged QKV output width (3 * 768)

// Scratch (static device globals — allocation-free per harness rules)
__device__ float g_v[(size_t)BH_*T_*D_];
__device__ __nv_bfloat16 g_x2[(size_t)BT_*K2];
__device__ __nv_bfloat16 g_ctx2[(size_t)BT_*K2];
__device__ __nv_bfloat16 g_wqkv2[(size_t)N3*K2];
__device__ __nv_bfloat16 g_wo2[(size_t)C_*K2];
__device__ __nv_bfloat16 g_q2[(size_t)BH_*T_*D2];
__device__ __nv_bfloat16 g_k2[(size_t)BH_*T_*D2];
__device__ uint32_t g_vph[(size_t)BH_*(T_/2)*D_];
__device__ uint32_t g_vpl[(size_t)BH_*(T_/2)*D_];

// ---------------------------------------------------------------------------
// conversions
// ---------------------------------------------------------------------------
template<int ISW>
__global__ __launch_bounds__(256) void conv_hilo(const float* __restrict__ in,
                                                 __nv_bfloat16* __restrict__ out,
                                                 int nelem)
{
    int idx = blockIdx.x * 256 + threadIdx.x;
    if (idx >= nelem) return;
    int r = idx / C_, c = idx % C_;
    float x = in[idx];
    __nv_bfloat16 hi = __float2bfloat16(x);
    __nv_bfloat16 lo = __float2bfloat16(x - __bfloat162float(hi));
    __nv_bfloat16* o = out + (size_t)r * K2;
    if (ISW) { o[c] = hi; o[c + C_] = hi; o[c + 2*C_] = lo; }
    else     { o[c] = hi; o[c + C_] = lo; o[c + 2*C_] = hi; }
}

__global__ __launch_bounds__(256) void conv_vp(const float* __restrict__ in,
                                               uint32_t* __restrict__ vph,
                                               uint32_t* __restrict__ vpl,
                                               int nelem)
{
    int idx = blockIdx.x * 256 + threadIdx.x;
    if (idx >= nelem) return;
    int d  = idx & 63;
    int t2 = idx >> 6;
    float v0 = in[(size_t)(2*t2) * 64 + d];
    float v1 = in[(size_t)(2*t2) * 64 + 64 + d];
    __nv_bfloat16 h0 = __float2bfloat16(v0);
    __nv_bfloat16 h1 = __float2bfloat16(v1);
    __nv_bfloat16 l0 = __float2bfloat16(v0 - __bfloat162float(h0));
    __nv_bfloat16 l1 = __float2bfloat16(v1 - __bfloat162float(h1));
    __nv_bfloat162 hp = __halves2bfloat162(h0, h1);
    __nv_bfloat162 lp = __halves2bfloat162(l0, l1);
    vph[idx] = *(uint32_t*)&hp;
    vpl[idx] = *(uint32_t*)&lp;
}

// ---------------------------------------------------------------------------
// async + mma helpers
// ---------------------------------------------------------------------------
__device__ __forceinline__ void cp16(void* dst, const void* src)
{
    uint32_t d = (uint32_t)__cvta_generic_to_shared(dst);
    asm volatile("cp.async.cg.shared.global [%0], [%1], 16;\n" :: "r"(d), "l"(src));
}
__device__ __forceinline__ void cp_commit()  { asm volatile("cp.async.commit_group;\n" ::: "memory"); }
__device__ __forceinline__ void cp_wait2()   { asm volatile("cp.async.wait_group 2;\n" ::: "memory"); }
__device__ __forceinline__ void cp_wait1()   { asm volatile("cp.async.wait_group 1;\n" ::: "memory"); }
__device__ __forceinline__ void cp_wait0()   { asm volatile("cp.async.wait_group 0;\n" ::: "memory"); }

__device__ __forceinline__ void mma_bf16(float c[4], const uint32_t a[4], const uint32_t b[2])
{
    asm volatile(
        "mma.sync.aligned.m16n8k16.row.col.f32.bf16.bf16.f32 "
        "{%0,%1,%2,%3}, {%4,%5,%6,%7}, {%8,%9}, {%0,%1,%2,%3};"
        : "+f"(c[0]), "+f"(c[1]), "+f"(c[2]), "+f"(c[3])
        : "r"(a[0]), "r"(a[1]), "r"(a[2]), "r"(a[3]), "r"(b[0]), "r"(b[1]));
}
__device__ __forceinline__ void ldsm4(uint32_t& r0, uint32_t& r1, uint32_t& r2, uint32_t& r3,
                                      uint32_t addr)
{
    asm volatile("ldmatrix.sync.aligned.m8n8.x4.shared.b16 {%0,%1,%2,%3}, [%4];"
                 : "=r"(r0), "=r"(r1), "=r"(r2), "=r"(r3) : "r"(addr));
}

// ---------------------------------------------------------------------------
// HMMA merged QKV GEMM, 3-stage cp.async + ldmatrix (unchanged from R15).
// ---------------------------------------------------------------------------
#define SAS 40
#define NKC (K2/32)              // 72
#define STG_H (128*SAS)
#define STAGE_H (2*STG_H)
#define QKV_SMEM (3*STAGE_H*2)   // 61440 bytes

__global__ __launch_bounds__(256, 2) void gemm_qkv(
    const __nv_bfloat16* __restrict__ A, const __nv_bfloat16* __restrict__ W,
    __nv_bfloat16* __restrict__ q2o, __nv_bfloat16* __restrict__ k2o,
    float* __restrict__ vo)
{
    extern __shared__ __nv_bfloat16 dsm[];
    const uint32_t smem0 = (uint32_t)__cvta_generic_to_shared(dsm);

    const int tid  = threadIdx.x;
    const int wid  = tid >> 5, lane = tid & 31;
    const int m0   = blockIdx.y * 128, n0 = blockIdx.x * 128;
    const int wm   = (wid & 3) * 32;
    const int wn   = (wid >> 2) * 64;
    const int tq   = lane & 3;
    const int tg   = lane >> 2;

    const int lr  = tid >> 2;
    const int lc8 = (tid & 3) << 3;

    const int a_row_off = (lane & 7) + ((lane >> 3) & 1) * 8;
    const int a_col_off = ((lane >> 4) & 1) * 8;
    const int b_sub     = ((lane >> 4) & 1);
    const int b_row_off = (lane & 7);
    const int b_col_off = ((lane >> 3) & 1) * 8;

    float c[2][8][4];
    #pragma unroll
    for (int mb = 0; mb < 2; mb++)
        #pragma unroll
        for (int nb = 0; nb < 8; nb++)
            #pragma unroll
            for (int i = 0; i < 4; i++) c[mb][nb][i] = 0.f;

    auto issue = [&](int kc, int s) {
        __nv_bfloat16* sA = dsm + s * STAGE_H;
        __nv_bfloat16* sB = sA + STG_H;
        #pragma unroll
        for (int half = 0; half < 2; half++) {
            int r = lr + half * 64;
            cp16(&sA[r * SAS + lc8], A + (size_t)(m0 + r) * K2 + kc * 32 + lc8);
            cp16(&sB[r * SAS + lc8], W + (size_t)(n0 + r) * K2 + kc * 32 + lc8);
        }
    };

    issue(0, 0); cp_commit();
    issue(1, 1); cp_commit();

    for (int kc = 0; kc < NKC; kc++) {
        const int s = kc % 3;
        if (kc + 2 < NKC) { issue(kc + 2, (kc + 2) % 3); cp_commit(); cp_wait2(); }
        else if (kc + 1 < NKC) cp_wait1();
        else                   cp_wait0();
        __syncthreads();

        const uint32_t aBase = smem0 + (s * STAGE_H) * 2;
        const uint32_t bBase = aBase + STG_H * 2;

        #pragma unroll
        for (int ks = 0; ks < 32; ks += 16) {
            uint32_t af[2][4], bf[8][2];
            #pragma unroll
            for (int mb = 0; mb < 2; mb++) {
                const uint32_t addr = aBase +
                    ((wm + mb * 16 + a_row_off) * SAS + ks + a_col_off) * 2;
                ldsm4(af[mb][0], af[mb][1], af[mb][2], af[mb][3], addr);
            }
            #pragma unroll
            for (int np = 0; np < 4; np++) {
                const uint32_t addr = bBase +
                    ((wn + (np * 2 + b_sub) * 8 + b_row_off) * SAS + ks + b_col_off) * 2;
                ldsm4(bf[2*np][0], bf[2*np][1], bf[2*np+1][0], bf[2*np+1][1], addr);
            }
            #pragma unroll
            for (int mb = 0; mb < 2; mb++)
                #pragma unroll
                for (int nb = 0; nb < 8; nb++)
                    mma_bf16(c[mb][nb], af[mb], bf[nb]);
        }
        __syncthreads();
    }

    #pragma unroll
    for (int mb = 0; mb < 2; mb++) {
        #pragma unroll
        for (int nb = 0; nb < 8; nb++) {
            const int m = m0 + wm + mb * 16 + tg;
            const int n = n0 + wn + nb * 8 + tq * 2;
            const int sec  = n / 768;
            const int nloc = n - sec * 768;
            const int b = m >> 12, t = m & 4095;
            const int h = nloc >> 6, d = nloc & 63;
            if (sec == 2) {
                float* p = vo + (((size_t)(b * H_ + h)) * T_ + t) * D_ + d;
                *(float2*)p            = make_float2(c[mb][nb][0], c[mb][nb][1]);
                *(float2*)(p + 8 * D_) = make_float2(c[mb][nb][2], c[mb][nb][3]);
            } else {
                __nv_bfloat16* out = (sec == 0) ? q2o : k2o;
                #pragma unroll
                for (int half = 0; half < 2; half++) {
                    const float v0 = c[mb][nb][2*half + 0];
                    const float v1 = c[mb][nb][2*half + 1];
                    __nv_bfloat16 h0 = __float2bfloat16(v0);
                    __nv_bfloat16 h1 = __float2bfloat16(v1);
                    __nv_bfloat16 e0 = __float2bfloat16(v0 - __bfloat162float(h0));
                    __nv_bfloat16 e1 = __float2bfloat16(v1 - __bfloat162float(h1));
                    __nv_bfloat162 hp = __halves2bfloat162(h0, h1);
                    __nv_bfloat162 ep = __halves2bfloat162(e0, e1);
                    __nv_bfloat16* p = out + ((size_t)(b * H_ + h) * T_ + t + half * 8) * D2 + d;
                    if (sec == 0) {   // Q: [hi | lo | hi]
                        *(__nv_bfloat162*)(p)       = hp;
                        *(__nv_bfloat162*)(p + 64)  = ep;
                        *(__nv_bfloat162*)(p + 128) = hp;
                    } else {          // K: [hi | hi | lo]
                        *(__nv_bfloat162*)(p)       = hp;
                        *(__nv_bfloat162*)(p + 64)  = hp;
                        *(__nv_bfloat162*)(p + 128) = ep;
                    }
                }
            }
        }
    }
}

// ---------------------------------------------------------------------------
// HMMA O-projection GEMM, 2-stage cp.async + ldmatrix. NT=64 (unchanged).
// ---------------------------------------------------------------------------
__global__ __launch_bounds__(256, 2) void gemm_o(const __nv_bfloat16* __restrict__ A,
                                                 const __nv_bfloat16* __restrict__ Bm,
                                                 float* __restrict__ out)
{
    constexpr int NT = 64;
    constexpr int NB = 4;

    __shared__ __align__(16) __nv_bfloat16 sA[2][128][SAS];
    __shared__ __align__(16) __nv_bfloat16 sB[2][NT][SAS];

    const int tid  = threadIdx.x;
    const int wid  = tid >> 5, lane = tid & 31;
    const int m0   = blockIdx.y * 128, n0 = blockIdx.x * NT;
    const int wm   = (wid & 3) * 32;
    const int wn   = (wid >> 2) * (NT / 2);
    const int tq   = lane & 3;
    const int tg   = lane >> 2;

    const int lr  = tid >> 2;
    const int lc8 = (tid & 3) << 3;

    const int a_row_off = (lane & 7) + ((lane >> 3) & 1) * 8;
    const int a_col_off = ((lane >> 4) & 1) * 8;
    const int b_sub     = ((lane >> 4) & 1);
    const int b_row_off = (lane & 7);
    const int b_col_off = ((lane >> 3) & 1) * 8;

    const uint32_t sA0 = (uint32_t)__cvta_generic_to_shared(&sA[0][0][0]);
    const uint32_t sB0 = (uint32_t)__cvta_generic_to_shared(&sB[0][0][0]);

    float c[2][NB][4];
    #pragma unroll
    for (int mb = 0; mb < 2; mb++)
        #pragma unroll
        for (int nb = 0; nb < NB; nb++)
            #pragma unroll
            for (int i = 0; i < 4; i++) c[mb][nb][i] = 0.f;

    auto issue = [&](int kc, int s) {
        #pragma unroll
        for (int half = 0; half < 2; half++) {
            int r = lr + half * 64;
            cp16(&sA[s][r][lc8], A + (size_t)(m0 + r) * K2 + kc * 32 + lc8);
        }
        cp16(&sB[s][lr][lc8], Bm + (size_t)(n0 + lr) * K2 + kc * 32 + lc8);
    };

    issue(0, 0);
    cp_commit();

    for (int kc = 0; kc < NKC; kc++) {
        const int s = kc & 1;
        if (kc + 1 < NKC) { issue(kc + 1, s ^ 1); cp_commit(); cp_wait1(); }
        else              { cp_wait0(); }
        __syncthreads();

        const uint32_t aBase = sA0 + s * (128 * SAS * 2);
        const uint32_t bBase = sB0 + s * (NT * SAS * 2);

        #pragma unroll
        for (int ks = 0; ks < 32; ks += 16) {
            uint32_t af[2][4], bf[NB][2];
            #pragma unroll
            for (int mb = 0; mb < 2; mb++) {
                const uint32_t addr = aBase +
                    ((wm + mb * 16 + a_row_off) * SAS + ks + a_col_off) * 2;
                ldsm4(af[mb][0], af[mb][1], af[mb][2], af[mb][3], addr);
            }
            #pragma unroll
            for (int np = 0; np < 2; np++) {
                const uint32_t addr = bBase +
                    ((wn + (np * 2 + b_sub) * 8 + b_row_off) * SAS + ks + b_col_off) * 2;
                ldsm4(bf[2*np][0], bf[2*np][1], bf[2*np+1][0], bf[2*np+1][1], addr);
            }
            #pragma unroll
            for (int mb = 0; mb < 2; mb++)
                #pragma unroll
                for (int nb = 0; nb < NB; nb++)
                    mma_bf16(c[mb][nb], af[mb], bf[nb]);
        }
        __syncthreads();
    }

    #pragma unroll
    for (int mb = 0; mb < 2; mb++) {
        #pragma unroll
        for (int nb = 0; nb < NB; nb++) {
            const int m = m0 + wm + mb * 16 + tg;
            const int n = n0 + wn + nb * 8 + tq * 2;
            float* p = out + (size_t)m * C_ + n;
            *(float2*)p            = make_float2(c[mb][nb][0], c[mb][nb][1]);
            *(float2*)(p + 8 * C_) = make_float2(c[mb][nb][2], c[mb][nb][3]);
        }
    }
}

// ---------------------------------------------------------------------------
// HMMA causal flash attention: QK frags via ldmatrix; epilogue writes the
// [hi|lo|hi] ctx2 split directly (conv pass fused away).
// ---------------------------------------------------------------------------
#define SQS 100
#define SVS 72
#define ATTN_SMEM ((128*SQS + 64*SQS + 64*SVS) * 4)   // 95232 B

__global__ __launch_bounds__(256, 1) void attn_mma(const __nv_bfloat16* __restrict__ Q2,
                                                   const __nv_bfloat16* __restrict__ Ksp,
                                                   const uint32_t* __restrict__ Vph,
                                                   const uint32_t* __restrict__ Vpl,
                                                   __nv_bfloat16* __restrict__ ctx2)
{
    extern __shared__ uint32_t smem_u[];
    uint32_t* sQ = smem_u;
    uint32_t* sK = smem_u + 128 * SQS;
    uint32_t* sV = smem_u + 128 * SQS + 64 * SQS;
    const uint32_t sQb = (uint32_t)__cvta_generic_to_shared(sQ);
    const uint32_t sKb = (uint32_t)__cvta_generic_to_shared(sK);

    const int tid = threadIdx.x;
    const int w   = tid >> 5;
    const int lane = tid & 31;
    const int tg  = lane >> 2;
    const int tq  = lane & 3;
    const int qt  = blockIdx.x;
    const int bh  = blockIdx.y;
    const int qb  = qt * 128;
    const int rbase = qb + w * 16;
    const int row0 = rbase + tg;
    const int row1 = row0 + 8;

    const int a_row_off = (lane & 7) + ((lane >> 3) & 1) * 8;
    const int a_col_off = ((lane >> 4) & 1) * 8;
    const int b_sub     = ((lane >> 4) & 1);
    const int b_row_off = (lane & 7);
    const int b_col_off = ((lane >> 3) & 1) * 8;

    {
        const __nv_bfloat16* qsrc = Q2 + ((size_t)bh * T_ + qb) * D2;
        int r = tid >> 1;
        #pragma unroll
        for (int i = 0; i < 12; i++) {
            int c4 = (tid & 1) + 2 * i;
            *(uint4*)(sQ + r * SQS + c4 * 4) = *(const uint4*)(qsrc + (size_t)r * D2 + c4 * 8);
        }
    }

    float O[8][4];
    #pragma unroll
    for (int nb = 0; nb < 8; nb++)
        #pragma unroll
        for (int i = 0; i < 4; i++) O[nb][i] = 0.f;
    float m0 = -1e30f, m1 = -1e30f, l0 = 0.f, l1 = 0.f;

    const int nkt = 2 * qt + 2;
    for (int kt = 0; kt < nkt; kt++) {
        const int ktbase = kt * 64;
        __syncthreads();
        {
            int r  = tid >> 2;
            int cb = tid & 3;
            const __nv_bfloat16* ksrc = Ksp + ((size_t)bh * T_ + ktbase + r) * D2;
            #pragma unroll
            for (int i = 0; i < 6; i++) {
                int c4 = cb + 4 * i;
                *(uint4*)(sK + r * SQS + c4 * 4) = *(const uint4*)(ksrc + c4 * 8);
            }
            const uint32_t* vsrc = (r < 32)
                ? Vph + ((size_t)bh * (T_/2) + ktbase/2 + r) * 64
                : Vpl + ((size_t)bh * (T_/2) + ktbase/2 + (r - 32)) * 64;
            #pragma unroll
            for (int i = 0; i < 4; i++) {
                int c4 = cb + 4 * i;
                *(uint4*)(sV + r * SVS + c4 * 4) = *(const uint4*)(vsrc + c4 * 4);
            }
        }
        __syncthreads();

        if (ktbase > rbase + 15) continue;

        float S[8][4];
        #pragma unroll
        for (int nb = 0; nb < 8; nb++)
            #pragma unroll
            for (int i = 0; i < 4; i++) S[nb][i] = 0.f;

        #pragma unroll
        for (int ks = 0; ks < 12; ks++) {
            uint32_t a[4], b[8][2];
            ldsm4(a[0], a[1], a[2], a[3],
                  sQb + ((w*16 + a_row_off) * SQS + ks * 8) * 4 + a_col_off * 2);
            #pragma unroll
            for (int np = 0; np < 4; np++) {
                ldsm4(b[2*np][0], b[2*np][1], b[2*np+1][0], b[2*np+1][1],
                      sKb + (((np*2 + b_sub) * 8 + b_row_off) * SQS + ks * 8) * 4 + b_col_off * 2);
            }
            #pragma unroll
            for (int nb = 0; nb < 8; nb++)
                mma_bf16(S[nb], a, b[nb]);
        }

        #pragma unroll
        for (int nb = 0; nb < 8; nb++)
            #pragma unroll
            for (int i = 0; i < 4; i++) S[nb][i] *= 0.125f;

        if (ktbase + 63 > rbase) {
            #pragma unroll
            for (int nb = 0; nb < 8; nb++) {
                int col0 = ktbase + nb*8 + 2*tq;
                int col1 = col0 + 1;
                if (col0 > row0) S[nb][0] = -1e30f;
                if (col1 > row0) S[nb][1] = -1e30f;
                if (col0 > row1) S[nb][2] = -1e30f;
                if (col1 > row1) S[nb][3] = -1e30f;
            }
        }

        float mx0 = -1e30f, mx1 = -1e30f;
        #pragma unroll
        for (int nb = 0; nb < 8; nb++) {
            mx0 = fmaxf(mx0, fmaxf(S[nb][0], S[nb][1]));
            mx1 = fmaxf(mx1, fmaxf(S[nb][2], S[nb][3]));
        }
        mx0 = fmaxf(mx0, __shfl_xor_sync(0xffffffffu, mx0, 1));
        mx0 = fmaxf(mx0, __shfl_xor_sync(0xffffffffu, mx0, 2));
        mx1 = fmaxf(mx1, __shfl_xor_sync(0xffffffffu, mx1, 1));
        mx1 = fmaxf(mx1, __shfl_xor_sync(0xffffffffu, mx1, 2));

        const float m0n = fmaxf(m0, mx0);
        const float m1n = fmaxf(m1, mx1);
        const float cr0 = __expf(m0 - m0n);
        const float cr1 = __expf(m1 - m1n);

        uint32_t phi0[8], phi1[8], plo0[8], plo1[8];
        float ps0 = 0.f, ps1 = 0.f;
        #pragma unroll
        for (int nb = 0; nb < 8; nb++) {
            float p00 = __expf(S[nb][0] - m0n);
            float p01 = __expf(S[nb][1] - m0n);
            float p10 = __expf(S[nb][2] - m1n);
            float p11 = __expf(S[nb][3] - m1n);
            ps0 += p00 + p01;
            ps1 += p10 + p11;
            __nv_bfloat162 h0 = __float22bfloat162_rn(make_float2(p00, p01));
            __nv_bfloat162 h1 = __float22bfloat162_rn(make_float2(p10, p11));
            phi0[nb] = *(uint32_t*)&h0;
            phi1[nb] = *(uint32_t*)&h1;
            __nv_bfloat162 e0 = __float22bfloat162_rn(make_float2(
                p00 - __bfloat162float(h0.x), p01 - __bfloat162float(h0.y)));
            __nv_bfloat162 e1 = __float22bfloat162_rn(make_float2(
                p10 - __bfloat162float(h1.x), p11 - __bfloat162float(h1.y)));
            plo0[nb] = *(uint32_t*)&e0;
            plo1[nb] = *(uint32_t*)&e1;
        }
        ps0 += __shfl_xor_sync(0xffffffffu, ps0, 1);
        ps0 += __shfl_xor_sync(0xffffffffu, ps0, 2);
        ps1 += __shfl_xor_sync(0xffffffffu, ps1, 1);
        ps1 += __shfl_xor_sync(0xffffffffu, ps1, 2);
        l0 = l0 * cr0 + ps0;  m0 = m0n;
        l1 = l1 * cr1 + ps1;  m1 = m1n;
        #pragma unroll
        for (int nb = 0; nb < 8; nb++) {
            O[nb][0] *= cr0; O[nb][1] *= cr0;
            O[nb][2] *= cr1; O[nb][3] *= cr1;
        }

        #pragma unroll
        for (int ks = 0; ks < 4; ks++) {
            uint32_t ahi[4] = { phi0[2*ks], phi1[2*ks], phi0[2*ks+1], phi1[2*ks+1] };
            uint32_t alo[4] = { plo0[2*ks], plo1[2*ks], plo0[2*ks+1], plo1[2*ks+1] };
            #pragma unroll
            for (int nb = 0; nb < 8; nb++) {
                uint32_t bhv[2];
                bhv[0] = sV[(ks*8 + tq    ) * SVS + nb*8 + tg];
                bhv[1] = sV[(ks*8 + tq + 4) * SVS + nb*8 + tg];
                mma_bf16(O[nb], ahi, bhv);
                mma_bf16(O[nb], alo, bhv);
            }
            #pragma unroll
            for (int nb = 0; nb < 8; nb++) {
                uint32_t blv[2];
                blv[0] = sV[(32 + ks*8 + tq    ) * SVS + nb*8 + tg];
                blv[1] = sV[(32 + ks*8 + tq + 4) * SVS + nb*8 + tg];
                mma_bf16(O[nb], ahi, blv);
            }
        }
    }

    // ---- epilogue: normalize + split [hi|lo|hi] directly into ctx2 ----
    const float inv0 = 1.f / l0;
    const float inv1 = 1.f / l1;
    const int b = bh / H_, h = bh % H_;
    #pragma unroll
    for (int nb = 0; nb < 8; nb++) {
        const int col = h * 64 + nb * 8 + 2 * tq;
        #pragma unroll
        for (int half = 0; half < 2; half++) {
            const int   row = half ? row1 : row0;
            const float inv = half ? inv1 : inv0;
            const float v0 = O[nb][2*half + 0] * inv;
            const float v1 = O[nb][2*half + 1] * inv;
            __nv_bfloat16 h0 = __float2bfloat16(v0);
            __nv_bfloat16 h1 = __float2bfloat16(v1);
            __nv_bfloat16 e0 = __float2bfloat16(v0 - __bfloat162float(h0));
            __nv_bfloat16 e1 = __float2bfloat16(v1 - __bfloat162float(h1));
            __nv_bfloat162 hp = __halves2bfloat162(h0, h1);
            __nv_bfloat162 ep = __halves2bfloat162(e0, e1);
            __nv_bfloat16* p = ctx2 + ((size_t)b * T_ + row) * K2 + col;
            *(__nv_bfloat162*)(p)         = hp;   // [hi
            *(__nv_bfloat162*)(p + 768)   = ep;   //  lo
            *(__nv_bfloat162*)(p + 1536)  = hp;   //  hi]
        }
    }
}

// ---------------------------------------------------------------------------
extern "C" void kernel_launch(void* const* d_in, const int* in_sizes, int n_in,
                              void* d_out, int out_size)
{
    (void)in_sizes; (void)n_in; (void)out_size;
    const float* x  = (const float*)d_in[0];
    const float* wq = (const float*)d_in[1];
    const float* wk = (const float*)d_in[2];
    const float* wv = (const float*)d_in[3];
    const float* wo = (const float*)d_in[4];
    float* out = (float*)d_out;

    float *v;
    __nv_bfloat16 *x2, *ctx2, *wqkv2, *wo2, *q2, *k2;
    uint32_t *vph, *vpl;
    cudaGetSymbolAddress((void**)&v,     g_v);
    cudaGetSymbolAddress((void**)&x2,    g_x2);
    cudaGetSymbolAddress((void**)&ctx2,  g_ctx2);
    cudaGetSymbolAddress((void**)&wqkv2, g_wqkv2);
    cudaGetSymbolAddress((void**)&wo2,   g_wo2);
    cudaGetSymbolAddress((void**)&q2,    g_q2);
    cudaGetSymbolAddress((void**)&k2,    g_k2);
    cudaGetSymbolAddress((void**)&vph,   g_vph);
    cudaGetSymbolAddress((void**)&vpl,   g_vpl);

    const int nx = BT_ * C_;
    const int nw = C_ * C_;
    conv_hilo<0><<<(nx + 255) / 256, 256>>>(x,  x2,  nx);
    conv_hilo<1><<<(nw + 255) / 256, 256>>>(wq, wqkv2,                      nw);
    conv_hilo<1><<<(nw + 255) / 256, 256>>>(wk, wqkv2 + (size_t)768  * K2, nw);
    conv_hilo<1><<<(nw + 255) / 256, 256>>>(wv, wqkv2 + (size_t)1536 * K2, nw);
    conv_hilo<1><<<(nw + 255) / 256, 256>>>(wo, wo2, nw);

    // merged QKV GEMM: grid 18 x 64, 3-stage pipeline
    cudaFuncSetAttribute(gemm_qkv, cudaFuncAttributeMaxDynamicSharedMemorySize, QKV_SMEM);
    gemm_qkv<<<dim3(N3 / 128, BT_ / 128), 256, QKV_SMEM>>>(x2, wqkv2, q2, k2, v);

    const int nvp = BH_ * (T_/2) * D_;
    conv_vp<<<(nvp + 255) / 256, 256>>>(v, vph, vpl, nvp);

    cudaFuncSetAttribute(attn_mma, cudaFuncAttributeMaxDynamicSharedMemorySize, ATTN_SMEM);
    attn_mma<<<dim3(T_ / 128, BH_), 256, ATTN_SMEM>>>(q2, k2, vph, vpl, ctx2);

    // O GEMM: HMMA 128x64 tile, grid 12 x 64 (reads fused ctx2)
    gemm_o<<<dim3(C_ / 64, BT_ / 128), 256>>>(ctx2, wo2, out);
}

// round 17
// speedup vs baseline: 1.5233x; 1.5233x over previous
#include <cuda_runtime.h>
#include <cuda_bf16.h>
#include <cstdint>
#include <math.h>

#define B_ 2
#define T_ 4096
#define H_ 12
#define D_ 64
#define C_ 768
#define BT_ (B_*T_)
#define BH_ (B_*H_)
#define K2 2304   // 3 * C_ : [hi | lo | hi] x [hi | hi | lo]
#define D2 192    // 3 * D_ for attention QK split
#define N3 2304   // merged QKV output width (3 * 768)

// Scratch (static device globals — allocation-free per harness rules)
__device__ float g_v[(size_t)BH_*T_*D_];
__device__ __nv_bfloat16 g_x2[(size_t)BT_*K2];
__device__ __nv_bfloat16 g_ctx2[(size_t)BT_*K2];
__device__ __nv_bfloat16 g_wqkv2[(size_t)N3*K2];
__device__ __nv_bfloat16 g_wo2[(size_t)C_*K2];
__device__ __nv_bfloat16 g_q2[(size_t)BH_*T_*D2];
__device__ __nv_bfloat16 g_k2[(size_t)BH_*T_*D2];
__device__ uint32_t g_vph[(size_t)BH_*(T_/2)*D_];
__device__ uint32_t g_vpl[(size_t)BH_*(T_/2)*D_];

// ---------------------------------------------------------------------------
// conversions
// ---------------------------------------------------------------------------
template<int ISW>
__global__ __launch_bounds__(256) void conv_hilo(const float* __restrict__ in,
                                                 __nv_bfloat16* __restrict__ out,
                                                 int nelem)
{
    int idx = blockIdx.x * 256 + threadIdx.x;
    if (idx >= nelem) return;
    int r = idx / C_, c = idx % C_;
    float x = in[idx];
    __nv_bfloat16 hi = __float2bfloat16(x);
    __nv_bfloat16 lo = __float2bfloat16(x - __bfloat162float(hi));
    __nv_bfloat16* o = out + (size_t)r * K2;
    if (ISW) { o[c] = hi; o[c + C_] = hi; o[c + 2*C_] = lo; }
    else     { o[c] = hi; o[c + C_] = lo; o[c + 2*C_] = hi; }
}

__global__ __launch_bounds__(256) void conv_vp(const float* __restrict__ in,
                                               uint32_t* __restrict__ vph,
                                               uint32_t* __restrict__ vpl,
                                               int nelem)
{
    int idx = blockIdx.x * 256 + threadIdx.x;
    if (idx >= nelem) return;
    int d  = idx & 63;
    int t2 = idx >> 6;
    float v0 = in[(size_t)(2*t2) * 64 + d];
    float v1 = in[(size_t)(2*t2) * 64 + 64 + d];
    __nv_bfloat16 h0 = __float2bfloat16(v0);
    __nv_bfloat16 h1 = __float2bfloat16(v1);
    __nv_bfloat16 l0 = __float2bfloat16(v0 - __bfloat162float(h0));
    __nv_bfloat16 l1 = __float2bfloat16(v1 - __bfloat162float(h1));
    __nv_bfloat162 hp = __halves2bfloat162(h0, h1);
    __nv_bfloat162 lp = __halves2bfloat162(l0, l1);
    vph[idx] = *(uint32_t*)&hp;
    vpl[idx] = *(uint32_t*)&lp;
}

// ---------------------------------------------------------------------------
// async + mma helpers
// ---------------------------------------------------------------------------
__device__ __forceinline__ void cp16(void* dst, const void* src)
{
    uint32_t d = (uint32_t)__cvta_generic_to_shared(dst);
    asm volatile("cp.async.cg.shared.global [%0], [%1], 16;\n" :: "r"(d), "l"(src));
}
__device__ __forceinline__ void cp_commit()  { asm volatile("cp.async.commit_group;\n" ::: "memory"); }
__device__ __forceinline__ void cp_wait2()   { asm volatile("cp.async.wait_group 2;\n" ::: "memory"); }
__device__ __forceinline__ void cp_wait1()   { asm volatile("cp.async.wait_group 1;\n" ::: "memory"); }
__device__ __forceinline__ void cp_wait0()   { asm volatile("cp.async.wait_group 0;\n" ::: "memory"); }

__device__ __forceinline__ void mma_bf16(float c[4], const uint32_t a[4], const uint32_t b[2])
{
    asm volatile(
        "mma.sync.aligned.m16n8k16.row.col.f32.bf16.bf16.f32 "
        "{%0,%1,%2,%3}, {%4,%5,%6,%7}, {%8,%9}, {%0,%1,%2,%3};"
        : "+f"(c[0]), "+f"(c[1]), "+f"(c[2]), "+f"(c[3])
        : "r"(a[0]), "r"(a[1]), "r"(a[2]), "r"(a[3]), "r"(b[0]), "r"(b[1]));
}
__device__ __forceinline__ void ldsm4(uint32_t& r0, uint32_t& r1, uint32_t& r2, uint32_t& r3,
                                      uint32_t addr)
{
    asm volatile("ldmatrix.sync.aligned.m8n8.x4.shared.b16 {%0,%1,%2,%3}, [%4];"
                 : "=r"(r0), "=r"(r1), "=r"(r2), "=r"(r3) : "r"(addr));
}

// ---------------------------------------------------------------------------
// HMMA merged QKV GEMM, 3-stage cp.async + ldmatrix (unchanged from R15).
// ---------------------------------------------------------------------------
#define SAS 40
#define NKC (K2/32)              // 72
#define STG_H (128*SAS)
#define STAGE_H (2*STG_H)
#define QKV_SMEM (3*STAGE_H*2)   // 61440 bytes

__global__ __launch_bounds__(256, 2) void gemm_qkv(
    const __nv_bfloat16* __restrict__ A, const __nv_bfloat16* __restrict__ W,
    __nv_bfloat16* __restrict__ q2o, __nv_bfloat16* __restrict__ k2o,
    float* __restrict__ vo)
{
    extern __shared__ __nv_bfloat16 dsm[];
    const uint32_t smem0 = (uint32_t)__cvta_generic_to_shared(dsm);

    const int tid  = threadIdx.x;
    const int wid  = tid >> 5, lane = tid & 31;
    const int m0   = blockIdx.y * 128, n0 = blockIdx.x * 128;
    const int wm   = (wid & 3) * 32;
    const int wn   = (wid >> 2) * 64;
    const int tq   = lane & 3;
    const int tg   = lane >> 2;

    const int lr  = tid >> 2;
    const int lc8 = (tid & 3) << 3;

    const int a_row_off = (lane & 7) + ((lane >> 3) & 1) * 8;
    const int a_col_off = ((lane >> 4) & 1) * 8;
    const int b_sub     = ((lane >> 4) & 1);
    const int b_row_off = (lane & 7);
    const int b_col_off = ((lane >> 3) & 1) * 8;

    float c[2][8][4];
    #pragma unroll
    for (int mb = 0; mb < 2; mb++)
        #pragma unroll
        for (int nb = 0; nb < 8; nb++)
            #pragma unroll
            for (int i = 0; i < 4; i++) c[mb][nb][i] = 0.f;

    auto issue = [&](int kc, int s) {
        __nv_bfloat16* sA = dsm + s * STAGE_H;
        __nv_bfloat16* sB = sA + STG_H;
        #pragma unroll
        for (int half = 0; half < 2; half++) {
            int r = lr + half * 64;
            cp16(&sA[r * SAS + lc8], A + (size_t)(m0 + r) * K2 + kc * 32 + lc8);
            cp16(&sB[r * SAS + lc8], W + (size_t)(n0 + r) * K2 + kc * 32 + lc8);
        }
    };

    issue(0, 0); cp_commit();
    issue(1, 1); cp_commit();

    for (int kc = 0; kc < NKC; kc++) {
        const int s = kc % 3;
        if (kc + 2 < NKC) { issue(kc + 2, (kc + 2) % 3); cp_commit(); cp_wait2(); }
        else if (kc + 1 < NKC) cp_wait1();
        else                   cp_wait0();
        __syncthreads();

        const uint32_t aBase = smem0 + (s * STAGE_H) * 2;
        const uint32_t bBase = aBase + STG_H * 2;

        #pragma unroll
        for (int ks = 0; ks < 32; ks += 16) {
            uint32_t af[2][4], bf[8][2];
            #pragma unroll
            for (int mb = 0; mb < 2; mb++) {
                const uint32_t addr = aBase +
                    ((wm + mb * 16 + a_row_off) * SAS + ks + a_col_off) * 2;
                ldsm4(af[mb][0], af[mb][1], af[mb][2], af[mb][3], addr);
            }
            #pragma unroll
            for (int np = 0; np < 4; np++) {
                const uint32_t addr = bBase +
                    ((wn + (np * 2 + b_sub) * 8 + b_row_off) * SAS + ks + b_col_off) * 2;
                ldsm4(bf[2*np][0], bf[2*np][1], bf[2*np+1][0], bf[2*np+1][1], addr);
            }
            #pragma unroll
            for (int mb = 0; mb < 2; mb++)
                #pragma unroll
                for (int nb = 0; nb < 8; nb++)
                    mma_bf16(c[mb][nb], af[mb], bf[nb]);
        }
        __syncthreads();
    }

    #pragma unroll
    for (int mb = 0; mb < 2; mb++) {
        #pragma unroll
        for (int nb = 0; nb < 8; nb++) {
            const int m = m0 + wm + mb * 16 + tg;
            const int n = n0 + wn + nb * 8 + tq * 2;
            const int sec  = n / 768;
            const int nloc = n - sec * 768;
            const int b = m >> 12, t = m & 4095;
            const int h = nloc >> 6, d = nloc & 63;
            if (sec == 2) {
                float* p = vo + (((size_t)(b * H_ + h)) * T_ + t) * D_ + d;
                *(float2*)p            = make_float2(c[mb][nb][0], c[mb][nb][1]);
                *(float2*)(p + 8 * D_) = make_float2(c[mb][nb][2], c[mb][nb][3]);
            } else {
                __nv_bfloat16* out = (sec == 0) ? q2o : k2o;
                #pragma unroll
                for (int half = 0; half < 2; half++) {
                    const float v0 = c[mb][nb][2*half + 0];
                    const float v1 = c[mb][nb][2*half + 1];
                    __nv_bfloat16 h0 = __float2bfloat16(v0);
                    __nv_bfloat16 h1 = __float2bfloat16(v1);
                    __nv_bfloat16 e0 = __float2bfloat16(v0 - __bfloat162float(h0));
                    __nv_bfloat16 e1 = __float2bfloat16(v1 - __bfloat162float(h1));
                    __nv_bfloat162 hp = __halves2bfloat162(h0, h1);
                    __nv_bfloat162 ep = __halves2bfloat162(e0, e1);
                    __nv_bfloat16* p = out + ((size_t)(b * H_ + h) * T_ + t + half * 8) * D2 + d;
                    if (sec == 0) {   // Q: [hi | lo | hi]
                        *(__nv_bfloat162*)(p)       = hp;
                        *(__nv_bfloat162*)(p + 64)  = ep;
                        *(__nv_bfloat162*)(p + 128) = hp;
                    } else {          // K: [hi | hi | lo]
                        *(__nv_bfloat162*)(p)       = hp;
                        *(__nv_bfloat162*)(p + 64)  = hp;
                        *(__nv_bfloat162*)(p + 128) = ep;
                    }
                }
            }
        }
    }
}

// ---------------------------------------------------------------------------
// HMMA O-projection GEMM, 2-stage cp.async + ldmatrix. NT=64 (unchanged).
// ---------------------------------------------------------------------------
__global__ __launch_bounds__(256, 2) void gemm_o(const __nv_bfloat16* __restrict__ A,
                                                 const __nv_bfloat16* __restrict__ Bm,
                                                 float* __restrict__ out)
{
    constexpr int NT = 64;
    constexpr int NB = 4;

    __shared__ __align__(16) __nv_bfloat16 sA[2][128][SAS];
    __shared__ __align__(16) __nv_bfloat16 sB[2][NT][SAS];

    const int tid  = threadIdx.x;
    const int wid  = tid >> 5, lane = tid & 31;
    const int m0   = blockIdx.y * 128, n0 = blockIdx.x * NT;
    const int wm   = (wid & 3) * 32;
    const int wn   = (wid >> 2) * (NT / 2);
    const int tq   = lane & 3;
    const int tg   = lane >> 2;

    const int lr  = tid >> 2;
    const int lc8 = (tid & 3) << 3;

    const int a_row_off = (lane & 7) + ((lane >> 3) & 1) * 8;
    const int a_col_off = ((lane >> 4) & 1) * 8;
    const int b_sub     = ((lane >> 4) & 1);
    const int b_row_off = (lane & 7);
    const int b_col_off = ((lane >> 3) & 1) * 8;

    const uint32_t sA0 = (uint32_t)__cvta_generic_to_shared(&sA[0][0][0]);
    const uint32_t sB0 = (uint32_t)__cvta_generic_to_shared(&sB[0][0][0]);

    float c[2][NB][4];
    #pragma unroll
    for (int mb = 0; mb < 2; mb++)
        #pragma unroll
        for (int nb = 0; nb < NB; nb++)
            #pragma unroll
            for (int i = 0; i < 4; i++) c[mb][nb][i] = 0.f;

    auto issue = [&](int kc, int s) {
        #pragma unroll
        for (int half = 0; half < 2; half++) {
            int r = lr + half * 64;
            cp16(&sA[s][r][lc8], A + (size_t)(m0 + r) * K2 + kc * 32 + lc8);
        }
        cp16(&sB[s][lr][lc8], Bm + (size_t)(n0 + lr) * K2 + kc * 32 + lc8);
    };

    issue(0, 0);
    cp_commit();

    for (int kc = 0; kc < NKC; kc++) {
        const int s = kc & 1;
        if (kc + 1 < NKC) { issue(kc + 1, s ^ 1); cp_commit(); cp_wait1(); }
        else              { cp_wait0(); }
        __syncthreads();

        const uint32_t aBase = sA0 + s * (128 * SAS * 2);
        const uint32_t bBase = sB0 + s * (NT * SAS * 2);

        #pragma unroll
        for (int ks = 0; ks < 32; ks += 16) {
            uint32_t af[2][4], bf[NB][2];
            #pragma unroll
            for (int mb = 0; mb < 2; mb++) {
                const uint32_t addr = aBase +
                    ((wm + mb * 16 + a_row_off) * SAS + ks + a_col_off) * 2;
                ldsm4(af[mb][0], af[mb][1], af[mb][2], af[mb][3], addr);
            }
            #pragma unroll
            for (int np = 0; np < 2; np++) {
                const uint32_t addr = bBase +
                    ((wn + (np * 2 + b_sub) * 8 + b_row_off) * SAS + ks + b_col_off) * 2;
                ldsm4(bf[2*np][0], bf[2*np][1], bf[2*np+1][0], bf[2*np+1][1], addr);
            }
            #pragma unroll
            for (int mb = 0; mb < 2; mb++)
                #pragma unroll
                for (int nb = 0; nb < NB; nb++)
                    mma_bf16(c[mb][nb], af[mb], bf[nb]);
        }
        __syncthreads();
    }

    #pragma unroll
    for (int mb = 0; mb < 2; mb++) {
        #pragma unroll
        for (int nb = 0; nb < NB; nb++) {
            const int m = m0 + wm + mb * 16 + tg;
            const int n = n0 + wn + nb * 8 + tq * 2;
            float* p = out + (size_t)m * C_ + n;
            *(float2*)p            = make_float2(c[mb][nb][0], c[mb][nb][1]);
            *(float2*)(p + 8 * C_) = make_float2(c[mb][nb][2], c[mb][nb][3]);
        }
    }
}

// ---------------------------------------------------------------------------
// HMMA causal flash attention: scalar-LDS QK frags (R15-proven form);
// epilogue writes the [hi|lo|hi] ctx2 split directly (conv pass fused away).
// ---------------------------------------------------------------------------
#define SQS 100
#define SVS 72
#define ATTN_SMEM ((128*SQS + 64*SQS + 64*SVS) * 4)   // 95232 B

__global__ __launch_bounds__(256, 1) void attn_mma(const __nv_bfloat16* __restrict__ Q2,
                                                   const __nv_bfloat16* __restrict__ Ksp,
                                                   const uint32_t* __restrict__ Vph,
                                                   const uint32_t* __restrict__ Vpl,
                                                   __nv_bfloat16* __restrict__ ctx2)
{
    extern __shared__ uint32_t smem_u[];
    uint32_t* sQ = smem_u;
    uint32_t* sK = smem_u + 128 * SQS;
    uint32_t* sV = smem_u + 128 * SQS + 64 * SQS;

    const int tid = threadIdx.x;
    const int w   = tid >> 5;
    const int lane = tid & 31;
    const int tg  = lane >> 2;
    const int tq  = lane & 3;
    const int qt  = blockIdx.x;
    const int bh  = blockIdx.y;
    const int qb  = qt * 128;
    const int rbase = qb + w * 16;
    const int row0 = rbase + tg;
    const int row1 = row0 + 8;

    {
        const __nv_bfloat16* qsrc = Q2 + ((size_t)bh * T_ + qb) * D2;
        int r = tid >> 1;
        #pragma unroll
        for (int i = 0; i < 12; i++) {
            int c4 = (tid & 1) + 2 * i;
            *(uint4*)(sQ + r * SQS + c4 * 4) = *(const uint4*)(qsrc + (size_t)r * D2 + c4 * 8);
        }
    }

    float O[8][4];
    #pragma unroll
    for (int nb = 0; nb < 8; nb++)
        #pragma unroll
        for (int i = 0; i < 4; i++) O[nb][i] = 0.f;
    float m0 = -1e30f, m1 = -1e30f, l0 = 0.f, l1 = 0.f;

    const int nkt = 2 * qt + 2;
    for (int kt = 0; kt < nkt; kt++) {
        const int ktbase = kt * 64;
        __syncthreads();
        {
            int r  = tid >> 2;
            int cb = tid & 3;
            const __nv_bfloat16* ksrc = Ksp + ((size_t)bh * T_ + ktbase + r) * D2;
            #pragma unroll
            for (int i = 0; i < 6; i++) {
                int c4 = cb + 4 * i;
                *(uint4*)(sK + r * SQS + c4 * 4) = *(const uint4*)(ksrc + c4 * 8);
            }
            const uint32_t* vsrc = (r < 32)
                ? Vph + ((size_t)bh * (T_/2) + ktbase/2 + r) * 64
                : Vpl + ((size_t)bh * (T_/2) + ktbase/2 + (r - 32)) * 64;
            #pragma unroll
            for (int i = 0; i < 4; i++) {
                int c4 = cb + 4 * i;
                *(uint4*)(sV + r * SVS + c4 * 4) = *(const uint4*)(vsrc + c4 * 4);
            }
        }
        __syncthreads();

        if (ktbase > rbase + 15) continue;

        float S[8][4];
        #pragma unroll
        for (int nb = 0; nb < 8; nb++)
            #pragma unroll
            for (int i = 0; i < 4; i++) S[nb][i] = 0.f;

        #pragma unroll
        for (int ks = 0; ks < 12; ks++) {
            uint32_t a[4];
            a[0] = sQ[(w*16 + tg    ) * SQS + ks*8 + tq    ];
            a[1] = sQ[(w*16 + tg + 8) * SQS + ks*8 + tq    ];
            a[2] = sQ[(w*16 + tg    ) * SQS + ks*8 + tq + 4];
            a[3] = sQ[(w*16 + tg + 8) * SQS + ks*8 + tq + 4];
            #pragma unroll
            for (int nb = 0; nb < 8; nb++) {
                uint32_t b[2];
                b[0] = sK[(nb*8 + tg) * SQS + ks*8 + tq    ];
                b[1] = sK[(nb*8 + tg) * SQS + ks*8 + tq + 4];
                mma_bf16(S[nb], a, b);
            }
        }

        #pragma unroll
        for (int nb = 0; nb < 8; nb++)
            #pragma unroll
            for (int i = 0; i < 4; i++) S[nb][i] *= 0.125f;

        if (ktbase + 63 > rbase) {
            #pragma unroll
            for (int nb = 0; nb < 8; nb++) {
                int col0 = ktbase + nb*8 + 2*tq;
                int col1 = col0 + 1;
                if (col0 > row0) S[nb][0] = -1e30f;
                if (col1 > row0) S[nb][1] = -1e30f;
                if (col0 > row1) S[nb][2] = -1e30f;
                if (col1 > row1) S[nb][3] = -1e30f;
            }
        }

        float mx0 = -1e30f, mx1 = -1e30f;
        #pragma unroll
        for (int nb = 0; nb < 8; nb++) {
            mx0 = fmaxf(mx0, fmaxf(S[nb][0], S[nb][1]));
            mx1 = fmaxf(mx1, fmaxf(S[nb][2], S[nb][3]));
        }
        mx0 = fmaxf(mx0, __shfl_xor_sync(0xffffffffu, mx0, 1));
        mx0 = fmaxf(mx0, __shfl_xor_sync(0xffffffffu, mx0, 2));
        mx1 = fmaxf(mx1, __shfl_xor_sync(0xffffffffu, mx1, 1));
        mx1 = fmaxf(mx1, __shfl_xor_sync(0xffffffffu, mx1, 2));

        const float m0n = fmaxf(m0, mx0);
        const float m1n = fmaxf(m1, mx1);
        const float cr0 = __expf(m0 - m0n);
        const float cr1 = __expf(m1 - m1n);

        uint32_t phi0[8], phi1[8], plo0[8], plo1[8];
        float ps0 = 0.f, ps1 = 0.f;
        #pragma unroll
        for (int nb = 0; nb < 8; nb++) {
            float p00 = __expf(S[nb][0] - m0n);
            float p01 = __expf(S[nb][1] - m0n);
            float p10 = __expf(S[nb][2] - m1n);
            float p11 = __expf(S[nb][3] - m1n);
            ps0 += p00 + p01;
            ps1 += p10 + p11;
            __nv_bfloat162 h0 = __float22bfloat162_rn(make_float2(p00, p01));
            __nv_bfloat162 h1 = __float22bfloat162_rn(make_float2(p10, p11));
            phi0[nb] = *(uint32_t*)&h0;
            phi1[nb] = *(uint32_t*)&h1;
            __nv_bfloat162 e0 = __float22bfloat162_rn(make_float2(
                p00 - __bfloat162float(h0.x), p01 - __bfloat162float(h0.y)));
            __nv_bfloat162 e1 = __float22bfloat162_rn(make_float2(
                p10 - __bfloat162float(h1.x), p11 - __bfloat162float(h1.y)));
            plo0[nb] = *(uint32_t*)&e0;
            plo1[nb] = *(uint32_t*)&e1;
        }
        ps0 += __shfl_xor_sync(0xffffffffu, ps0, 1);
        ps0 += __shfl_xor_sync(0xffffffffu, ps0, 2);
        ps1 += __shfl_xor_sync(0xffffffffu, ps1, 1);
        ps1 += __shfl_xor_sync(0xffffffffu, ps1, 2);
        l0 = l0 * cr0 + ps0;  m0 = m0n;
        l1 = l1 * cr1 + ps1;  m1 = m1n;
        #pragma unroll
        for (int nb = 0; nb < 8; nb++) {
            O[nb][0] *= cr0; O[nb][1] *= cr0;
            O[nb][2] *= cr1; O[nb][3] *= cr1;
        }

        #pragma unroll
        for (int ks = 0; ks < 4; ks++) {
            uint32_t ahi[4] = { phi0[2*ks], phi1[2*ks], phi0[2*ks+1], phi1[2*ks+1] };
            uint32_t alo[4] = { plo0[2*ks], plo1[2*ks], plo0[2*ks+1], plo1[2*ks+1] };
            #pragma unroll
            for (int nb = 0; nb < 8; nb++) {
                uint32_t bhv[2];
                bhv[0] = sV[(ks*8 + tq    ) * SVS + nb*8 + tg];
                bhv[1] = sV[(ks*8 + tq + 4) * SVS + nb*8 + tg];
                mma_bf16(O[nb], ahi, bhv);
                mma_bf16(O[nb], alo, bhv);
            }
            #pragma unroll
            for (int nb = 0; nb < 8; nb++) {
                uint32_t blv[2];
                blv[0] = sV[(32 + ks*8 + tq    ) * SVS + nb*8 + tg];
                blv[1] = sV[(32 + ks*8 + tq + 4) * SVS + nb*8 + tg];
                mma_bf16(O[nb], ahi, blv);
            }
        }
    }

    // ---- epilogue: normalize + split [hi|lo|hi] directly into ctx2 ----
    const float inv0 = 1.f / l0;
    const float inv1 = 1.f / l1;
    const int b = bh / H_, h = bh % H_;
    #pragma unroll
    for (int nb = 0; nb < 8; nb++) {
        const int col = h * 64 + nb * 8 + 2 * tq;
        #pragma unroll
        for (int half = 0; half < 2; half++) {
            const int   row = half ? row1 : row0;
            const float inv = half ? inv1 : inv0;
            const float v0 = O[nb][2*half + 0] * inv;
            const float v1 = O[nb][2*half + 1] * inv;
            __nv_bfloat16 h0 = __float2bfloat16(v0);
            __nv_bfloat16 h1 = __float2bfloat16(v1);
            __nv_bfloat16 e0 = __float2bfloat16(v0 - __bfloat162float(h0));
            __nv_bfloat16 e1 = __float2bfloat16(v1 - __bfloat162float(h1));
            __nv_bfloat162 hp = __halves2bfloat162(h0, h1);
            __nv_bfloat162 ep = __halves2bfloat162(e0, e1);
            __nv_bfloat16* p = ctx2 + ((size_t)b * T_ + row) * K2 + col;
            *(__nv_bfloat162*)(p)         = hp;   // [hi
            *(__nv_bfloat162*)(p + 768)   = ep;   //  lo
            *(__nv_bfloat162*)(p + 1536)  = hp;   //  hi]
        }
    }
}

// ---------------------------------------------------------------------------
extern "C" void kernel_launch(void* const* d_in, const int* in_sizes, int n_in,
                              void* d_out, int out_size)
{
    (void)in_sizes; (void)n_in; (void)out_size;
    const float* x  = (const float*)d_in[0];
    const float* wq = (const float*)d_in[1];
    const float* wk = (const float*)d_in[2];
    const float* wv = (const float*)d_in[3];
    const float* wo = (const float*)d_in[4];
    float* out = (float*)d_out;

    float *v;
    __nv_bfloat16 *x2, *ctx2, *wqkv2, *wo2, *q2, *k2;
    uint32_t *vph, *vpl;
    cudaGetSymbolAddress((void**)&v,     g_v);
    cudaGetSymbolAddress((void**)&x2,    g_x2);
    cudaGetSymbolAddress((void**)&ctx2,  g_ctx2);
    cudaGetSymbolAddress((void**)&wqkv2, g_wqkv2);
    cudaGetSymbolAddress((void**)&wo2,   g_wo2);
    cudaGetSymbolAddress((void**)&q2,    g_q2);
    cudaGetSymbolAddress((void**)&k2,    g_k2);
    cudaGetSymbolAddress((void**)&vph,   g_vph);
    cudaGetSymbolAddress((void**)&vpl,   g_vpl);

    const int nx = BT_ * C_;
    const int nw = C_ * C_;
    conv_hilo<0><<<(nx + 255) / 256, 256>>>(x,  x2,  nx);
    conv_hilo<1><<<(nw + 255) / 256, 256>>>(wq, wqkv2,                      nw);
    conv_hilo<1><<<(nw + 255) / 256, 256>>>(wk, wqkv2 + (size_t)768  * K2, nw);
    conv_hilo<1><<<(nw + 255) / 256, 256>>>(wv, wqkv2 + (size_t)1536 * K2, nw);
    conv_hilo<1><<<(nw + 255) / 256, 256>>>(wo, wo2, nw);

    // merged QKV GEMM: grid 18 x 64, 3-stage pipeline
    cudaFuncSetAttribute(gemm_qkv, cudaFuncAttributeMaxDynamicSharedMemorySize, QKV_SMEM);
    gemm_qkv<<<dim3(N3 / 128, BT_ / 128), 256, QKV_SMEM>>>(x2, wqkv2, q2, k2, v);

    const int nvp = BH_ * (T_/2) * D_;
    conv_vp<<<(nvp + 255) / 256, 256>>>(v, vph, vpl, nvp);

    cudaFuncSetAttribute(attn_mma, cudaFuncAttributeMaxDynamicSharedMemorySize, ATTN_SMEM);
    attn_mma<<<dim3(T_ / 128, BH_), 256, ATTN_SMEM>>>(q2, k2, vph, vpl, ctx2);

    // O GEMM: HMMA 128x64 tile, grid 12 x 64 (reads fused ctx2)
    gemm_o<<<dim3(C_ / 64, BT_ / 128), 256>>>(ctx2, wo2, out);
}